// round 6
// baseline (speedup 1.0000x reference)
#include <cuda_runtime.h>
#include <cuda_bf16.h>

#define NX 2048
#define NY 4096

// Coefficient tables (__device__ globals — allocations are forbidden).
// y-direction: SoA so 4 consecutive j load as one float4 each. d2 premult by mu.
__device__ float g_c1ya[NY], g_c1yb[NY], g_c1yc[NY];
__device__ float g_c2ya[NY], g_c2yb[NY], g_c2yc[NY];
// x-direction: PERMUTED to tap order (TA, TB, center):
//   interior i : TA=row i-1, TB=row i+1, center=i   -> coeffs (a, c, b)
//   i == 0     : TA=row 1,   TB=row 2,   center=0   -> coeffs (b, c, a)
//   i == NX-1  : TA=row NX-3,TB=row NX-2,center=NX-1-> coeffs (a, b, c)
__device__ float4 g_cx1[NX];
__device__ float4 g_cx2[NX];  // mu-folded

__device__ __forceinline__ void deriv_coeffs(const float* __restrict__ g, int n, int idx,
                                             float3& d1, float3& d2) {
    if (idx == 0) {
        float hA = g[1] - g[0];
        float hB = g[2] - g[1];
        d1.x = -(2.0f * hA + hB) / (hA * (hA + hB));
        d1.y = (hA + hB) / (hA * hB);
        d1.z = -hA / (hB * (hA + hB));
        d2.x = 2.0f / (hA * (hA + hB));
        d2.y = -2.0f / (hA * hB);
        d2.z = 2.0f / (hB * (hA + hB));
    } else if (idx == n - 1) {
        float hC = g[n - 2] - g[n - 3];
        float hD = g[n - 1] - g[n - 2];
        d1.x = hD / (hC * (hC + hD));
        d1.y = -(hC + hD) / (hC * hD);
        d1.z = (hC + 2.0f * hD) / (hD * (hC + hD));
        d2.x = 2.0f / (hC * (hC + hD));
        d2.y = -2.0f / (hC * hD);
        d2.z = 2.0f / (hD * (hC + hD));
    } else {
        float h1 = g[idx] - g[idx - 1];
        float h2 = g[idx + 1] - g[idx];
        d1.x = -h2 / (h1 * (h1 + h2));
        d1.y = (h2 - h1) / (h1 * h2);
        d1.z = h1 / (h2 * (h1 + h2));
        d2.x = 2.0f / (h1 * (h1 + h2));
        d2.y = -2.0f / (h1 * h2);
        d2.z = 2.0f / (h2 * (h1 + h2));
    }
}

__global__ void coeff_kernel(const float* __restrict__ x, const float* __restrict__ y,
                             const float* __restrict__ mu_p) {
    const float mu = mu_p[0];
    int t = blockIdx.x * blockDim.x + threadIdx.x;
    if (t < NY) {
        float3 d1, d2;
        deriv_coeffs(y, NY, t, d1, d2);
        g_c1ya[t] = d1.x; g_c1yb[t] = d1.y; g_c1yc[t] = d1.z;
        g_c2ya[t] = mu * d2.x; g_c2yb[t] = mu * d2.y; g_c2yc[t] = mu * d2.z;
    } else if (t < NY + NX) {
        int i = t - NY;
        float3 d1, d2;
        deriv_coeffs(x, NX, i, d1, d2);
        float4 p1, p2;  // permuted: (coeff_TA, coeff_TB, coeff_center, 0)
        if (i == 0) {
            p1 = make_float4(d1.y, d1.z, d1.x, 0.f);
            p2 = make_float4(d2.y, d2.z, d2.x, 0.f);
        } else if (i == NX - 1) {
            p1 = make_float4(d1.x, d1.y, d1.z, 0.f);
            p2 = make_float4(d2.x, d2.y, d2.z, 0.f);
        } else {
            p1 = make_float4(d1.x, d1.z, d1.y, 0.f);
            p2 = make_float4(d2.x, d2.z, d2.y, 0.f);
        }
        g_cx1[i] = p1;
        g_cx2[i] = make_float4(mu * p2.x, mu * p2.y, mu * p2.z, 0.f);
    }
}

// Each thread: 4 consecutive j (float4) x 2 consecutive rows (i0, i0+1).
__global__ __launch_bounds__(128) void rhs_kernel(const float* __restrict__ state,
                                                  float* __restrict__ out) {
    const int j4 = (blockIdx.x * 128 + threadIdx.x) * 4;
    const int i0 = blockIdx.y * 2;
    const int i1 = i0 + 1;
    const int lane = threadIdx.x & 31;

    const float* __restrict__ u = state;
    const float* __restrict__ v = state + (size_t)NX * NY;
    const size_t row0 = (size_t)i0 * NY;
    const size_t row1 = (size_t)i1 * NY;

    // ---- center rows (each is also the other's x-tap) ----
    const float4 uc0 = __ldg((const float4*)(u + row0 + j4));
    const float4 vc0 = __ldg((const float4*)(v + row0 + j4));
    const float4 uc1 = __ldg((const float4*)(u + row1 + j4));
    const float4 vc1 = __ldg((const float4*)(v + row1 + j4));

    // ---- x halo rows (clamped indices at grid edges; unused taps masked by
    //      the block-uniform selects below) ----
    const int rlo = max(i0 - 1, 0);
    const int rhi = min(i0 + 2, NX - 1);
    const float4 uhl = __ldg((const float4*)(u + (size_t)rlo * NY + j4));
    const float4 vhl = __ldg((const float4*)(v + (size_t)rlo * NY + j4));
    const float4 uhh = __ldg((const float4*)(u + (size_t)rhi * NY + j4));
    const float4 vhh = __ldg((const float4*)(v + (size_t)rhi * NY + j4));

    // ---- y halos via warp shuffle; warp-edge lanes fetch scalars ----
    float up0 = __shfl_up_sync(0xffffffffu, uc0.w, 1);
    float vp0 = __shfl_up_sync(0xffffffffu, vc0.w, 1);
    float up1 = __shfl_up_sync(0xffffffffu, uc1.w, 1);
    float vp1 = __shfl_up_sync(0xffffffffu, vc1.w, 1);
    float un0 = __shfl_down_sync(0xffffffffu, uc0.x, 1);
    float vn0 = __shfl_down_sync(0xffffffffu, vc0.x, 1);
    float un1 = __shfl_down_sync(0xffffffffu, uc1.x, 1);
    float vn1 = __shfl_down_sync(0xffffffffu, vc1.x, 1);
    if (lane == 0 && j4 > 0) {
        up0 = __ldg(u + row0 + j4 - 1);
        vp0 = __ldg(v + row0 + j4 - 1);
        up1 = __ldg(u + row1 + j4 - 1);
        vp1 = __ldg(v + row1 + j4 - 1);
    }
    if (lane == 31 && j4 + 4 < NY) {
        un0 = __ldg(u + row0 + j4 + 4);
        vn0 = __ldg(v + row0 + j4 + 4);
        un1 = __ldg(u + row1 + j4 + 4);
        vn1 = __ldg(v + row1 + j4 + 4);
    }

    // ---- y coefficients (SHARED across both rows — key amortization) ----
    const float4 c1a = __ldg((const float4*)(g_c1ya + j4));
    const float4 c1b = __ldg((const float4*)(g_c1yb + j4));
    const float4 c1c = __ldg((const float4*)(g_c1yc + j4));
    const float4 c2a = __ldg((const float4*)(g_c2ya + j4));  // mu-folded
    const float4 c2b = __ldg((const float4*)(g_c2yb + j4));
    const float4 c2c = __ldg((const float4*)(g_c2yc + j4));
    const float4 cxA0 = g_cx1[i0];
    const float4 cxB0 = g_cx2[i0];  // mu-folded
    const float4 cxA1 = g_cx1[i1];
    const float4 cxB1 = g_cx2[i1];

    // ---- x-tap operand selection (block-uniform; matches permuted coeffs) ----
    // row0: interior -> (TA,TB) = (halo_lo, center1) ; i0==0 -> (center1, halo_hi)
    // row1: interior -> (TA,TB) = (center0, halo_hi) ; i1==NX-1 -> (halo_lo, center0)
    const bool lo = (i0 == 0);
    const bool hi = (i1 == NX - 1);
    const float4 TAu0 = lo ? uc1 : uhl, TBu0 = lo ? uhh : uc1;
    const float4 TAv0 = lo ? vc1 : vhl, TBv0 = lo ? vhh : vc1;
    const float4 TAu1 = hi ? uhl : uc0, TBu1 = hi ? uc0 : uhh;
    const float4 TAv1 = hi ? vhl : vc0, TBv1 = hi ? vc0 : vhh;

    // ---- j-boundary tap shifts (k=0 / k=3 only) ----
    const bool jlo = (j4 == 0);
    const bool jhi = (j4 + 4 == NY);
    const float u0L0 = jlo ? uc0.x : up0, u0C0 = jlo ? uc0.y : uc0.x, u0R0 = jlo ? uc0.z : uc0.y;
    const float v0L0 = jlo ? vc0.x : vp0, v0C0 = jlo ? vc0.y : vc0.x, v0R0 = jlo ? vc0.z : vc0.y;
    const float u3L0 = jhi ? uc0.y : uc0.z, u3C0 = jhi ? uc0.z : uc0.w, u3R0 = jhi ? uc0.w : un0;
    const float v3L0 = jhi ? vc0.y : vc0.z, v3C0 = jhi ? vc0.z : vc0.w, v3R0 = jhi ? vc0.w : vn0;
    const float u0L1 = jlo ? uc1.x : up1, u0C1 = jlo ? uc1.y : uc1.x, u0R1 = jlo ? uc1.z : uc1.y;
    const float v0L1 = jlo ? vc1.x : vp1, v0C1 = jlo ? vc1.y : vc1.x, v0R1 = jlo ? vc1.z : vc1.y;
    const float u3L1 = jhi ? uc1.y : uc1.z, u3C1 = jhi ? uc1.z : uc1.w, u3R1 = jhi ? uc1.w : un1;
    const float v3L1 = jhi ? vc1.y : vc1.z, v3C1 = jhi ? vc1.z : vc1.w, v3R1 = jhi ? vc1.w : vn1;

    float4 du0, dv0, du1, dv1;

    // One output point: row r, component cmp.
#define PT(cmp, uL, uC, uR, vL, vC, vR, ucr, vcr, TAu, TBu, TAv, TBv, cx1r, cx2r, dur, dvr) \
    do {                                                                                    \
        const float d1yu = c1a.cmp * (uL) + c1b.cmp * (uC) + c1c.cmp * (uR);                \
        const float m2yu = c2a.cmp * (uL) + c2b.cmp * (uC) + c2c.cmp * (uR);                \
        const float d1yv = c1a.cmp * (vL) + c1b.cmp * (vC) + c1c.cmp * (vR);                \
        const float m2yv = c2a.cmp * (vL) + c2b.cmp * (vC) + c2c.cmp * (vR);                \
        const float d1xu = cx1r.x * TAu.cmp + cx1r.y * TBu.cmp + cx1r.z * ucr.cmp;          \
        const float m2xu = cx2r.x * TAu.cmp + cx2r.y * TBu.cmp + cx2r.z * ucr.cmp;          \
        const float d1xv = cx1r.x * TAv.cmp + cx1r.y * TBv.cmp + cx1r.z * vcr.cmp;          \
        const float m2xv = cx2r.x * TAv.cmp + cx2r.y * TBv.cmp + cx2r.z * vcr.cmp;          \
        dur.cmp = m2yu + m2xu - ucr.cmp * d1xu - vcr.cmp * d1yu + 0.01f;                    \
        dvr.cmp = m2yv + m2xv - ucr.cmp * d1xv - vcr.cmp * d1yv;                            \
    } while (0)

    // Row 0
    PT(x, u0L0, u0C0, u0R0, v0L0, v0C0, v0R0, uc0, vc0, TAu0, TBu0, TAv0, TBv0, cxA0, cxB0, du0, dv0);
    PT(y, uc0.x, uc0.y, uc0.z, vc0.x, vc0.y, vc0.z, uc0, vc0, TAu0, TBu0, TAv0, TBv0, cxA0, cxB0, du0, dv0);
    PT(z, uc0.y, uc0.z, uc0.w, vc0.y, vc0.z, vc0.w, uc0, vc0, TAu0, TBu0, TAv0, TBv0, cxA0, cxB0, du0, dv0);
    PT(w, u3L0, u3C0, u3R0, v3L0, v3C0, v3R0, uc0, vc0, TAu0, TBu0, TAv0, TBv0, cxA0, cxB0, du0, dv0);
    // Row 1
    PT(x, u0L1, u0C1, u0R1, v0L1, v0C1, v0R1, uc1, vc1, TAu1, TBu1, TAv1, TBv1, cxA1, cxB1, du1, dv1);
    PT(y, uc1.x, uc1.y, uc1.z, vc1.x, vc1.y, vc1.z, uc1, vc1, TAu1, TBu1, TAv1, TBv1, cxA1, cxB1, du1, dv1);
    PT(z, uc1.y, uc1.z, uc1.w, vc1.y, vc1.z, vc1.w, uc1, vc1, TAu1, TBu1, TAv1, TBv1, cxA1, cxB1, du1, dv1);
    PT(w, u3L1, u3C1, u3R1, v3L1, v3C1, v3R1, uc1, vc1, TAu1, TBu1, TAv1, TBv1, cxA1, cxB1, du1, dv1);
#undef PT

    // Boundary conditions:
    //   du[:, 0] = du[:, -1] = du[0, :] = 0 ; dv[:, 0] = dv[0, :] = 0
    if (lo) { du0 = make_float4(0.f, 0.f, 0.f, 0.f); dv0 = make_float4(0.f, 0.f, 0.f, 0.f); }
    if (jlo) { du0.x = 0.0f; dv0.x = 0.0f; du1.x = 0.0f; dv1.x = 0.0f; }
    if (jhi) { du0.w = 0.0f; du1.w = 0.0f; }

    const size_t voff = (size_t)NX * NY;
    *(float4*)(out + row0 + j4) = du0;
    *(float4*)(out + voff + row0 + j4) = dv0;
    *(float4*)(out + row1 + j4) = du1;
    *(float4*)(out + voff + row1 + j4) = dv1;
}

// Inputs (metadata order): t[1], state[2*NX*NY], x[NX], y[NY], mu[1]
extern "C" void kernel_launch(void* const* d_in, const int* in_sizes, int n_in,
                              void* d_out, int out_size) {
    const float* state = (const float*)d_in[1];
    const float* x     = (const float*)d_in[2];
    const float* y     = (const float*)d_in[3];
    const float* mu    = (const float*)d_in[4];
    float* out = (float*)d_out;

    {
        int total = NX + NY;
        int threads = 128;
        int blocks = (total + threads - 1) / threads;
        coeff_kernel<<<blocks, threads>>>(x, y, mu);
    }
    {
        dim3 block(128, 1, 1);
        dim3 grid(NY / 512, NX / 2, 1);  // 8 x 1024 blocks, 2 rows x 4 cols per thread
        rhs_kernel<<<grid, block>>>(state, out);
    }
}